// round 4
// baseline (speedup 1.0000x reference)
#include <cuda_runtime.h>
#include <stdint.h>

// AND-tree over last dim of (ROWS, 1024) binary float matrix.
// out[row] = 1.0f iff all 1024 elements == 1.0f (bit pattern 0x3F800000).
//
// One thread per row. Probe = first 64B of the row (4x uint4, issued with
// MLP=4 -> ONE DRAM round). Survival prob per row = 2^-16, so ~1 survivor
// expected chip-wide. Survivors are resolved warp-cooperatively: ballot
// finds them, the whole warp loads the full 4KB row as 8 independent strided
// uint4 per lane (one more DRAM round), single vote decides. No serial
// per-thread scan chains -> no tail-latency stragglers.

static constexpr int ROW_U4 = 1024 / 4;            // 256 uint4 per row
static constexpr unsigned ONE_BITS = 0x3F800000u;  // bit pattern of 1.0f
static constexpr int THREADS = 256;

__device__ __forceinline__ bool all_ones(uint4 v) {
    return v.x == ONE_BITS && v.y == ONE_BITS && v.z == ONE_BITS && v.w == ONE_BITS;
}

__global__ __launch_bounds__(THREADS) void vec_and_tree_kernel(
    const uint4* __restrict__ x, float* __restrict__ out, int rows)
{
    const int row = blockIdx.x * THREADS + threadIdx.x;
    if (row >= rows) return;                 // rows % THREADS == 0 -> full warps
    const int lane = threadIdx.x & 31;

    const uint4* rp = x + (size_t)row * ROW_U4;

    // Probe: 64B, 4 independent LDG.128 -> one DRAM round.
    uint4 a = rp[0], b = rp[1], c = rp[2], d = rp[3];
    bool ok = all_ones(a) & all_ones(b) & all_ones(c) & all_ones(d);

    // Rare survivors (2^-16 per row): resolve warp-cooperatively, one round each.
    unsigned surv = __ballot_sync(0xFFFFFFFFu, ok);
    while (surv) {
        const int l = __ffs(surv) - 1;
        surv &= surv - 1;
        const int srow = __shfl_sync(0xFFFFFFFFu, row, l);
        const uint4* sp = x + (size_t)srow * ROW_U4;

        bool lok = true;
        #pragma unroll
        for (int i = 0; i < ROW_U4 / 32; i++) {   // 8 independent loads, MLP=8
            lok &= all_ones(sp[i * 32 + lane]);
        }
        const bool rok = __all_sync(0xFFFFFFFFu, lok);
        if (lane == l) ok = rok;
    }

    out[row] = ok ? 1.0f : 0.0f;
}

extern "C" void kernel_launch(void* const* d_in, const int* in_sizes, int n_in,
                              void* d_out, int out_size)
{
    const uint4* x = (const uint4*)d_in[0];  // float32 bits reinterpreted
    float* out = (float*)d_out;

    const int rows = out_size;               // 65536
    const int blocks = (rows + THREADS - 1) / THREADS;  // 256

    vec_and_tree_kernel<<<blocks, THREADS>>>(x, out, rows);
}

// round 7
// speedup vs baseline: 1.0385x; 1.0385x over previous
#include <cuda_runtime.h>
#include <stdint.h>

// AND-tree over last dim of (ROWS, 1024) binary float matrix.
// out[row] = 1.0f iff all 1024 elements == 1.0f (bit pattern 0x3F800000).
//
// Floor analysis: every row needs >=1 probe; probes are 4KB apart so each
// opens a distinct DRAM row -> ~65536 activations ~ 6us cold. Warm (timed)
// replays keep the 8MB probe footprint L2-resident. This version minimizes
// everything else: 128 CTAs x 512 threads (exact cover, branchless clamp),
// 64B probe (survival 2^-16 -> ~zero survivors chip-wide) issued immediately
// with MLP=4, warp-cooperative one-round resolution for the rare survivor
// using streaming loads (__ldcs) so survivor rows never evict probe lines
// from L2 between replays.

static constexpr int ROW_U4 = 1024 / 4;            // 256 uint4 per row
static constexpr unsigned ONE_BITS = 0x3F800000u;  // bit pattern of 1.0f
static constexpr int THREADS = 512;

__device__ __forceinline__ bool all_ones(uint4 v) {
    return v.x == ONE_BITS && v.y == ONE_BITS && v.z == ONE_BITS && v.w == ONE_BITS;
}

__global__ __launch_bounds__(THREADS) void vec_and_tree_kernel(
    const uint4* __restrict__ x, float* __restrict__ out, int rows)
{
    // Branchless bounds handling: clamp. Duplicate threads recompute the same
    // row and write the same value (deterministic, benign).
    int row = blockIdx.x * THREADS + threadIdx.x;
    row = row < rows ? row : rows - 1;
    const int lane = threadIdx.x & 31;

    const uint4* rp = x + (size_t)row * ROW_U4;

    // Probe: first 64B of the row = one 128B line, 4 independent LDG.128
    // issued back-to-back (one DRAM/L2 round). Default caching: these lines
    // are re-read every graph replay and should stay L2-resident.
    uint4 a = rp[0], b = rp[1], c = rp[2], d = rp[3];
    bool ok = all_ones(a) & all_ones(b) & all_ones(c) & all_ones(d);

    // Survivors (prob 2^-16/row, ~1 chip-wide): resolve warp-cooperatively
    // in one extra round. Streaming loads -> don't pollute L2.
    unsigned surv = __ballot_sync(0xFFFFFFFFu, ok);
    while (surv) {
        const int l = __ffs(surv) - 1;
        surv &= surv - 1;
        const int srow = __shfl_sync(0xFFFFFFFFu, row, l);
        const uint4* sp = x + (size_t)srow * ROW_U4;

        bool lok = true;
        #pragma unroll
        for (int i = 0; i < ROW_U4 / 32; i++) {     // 8 independent loads, MLP=8
            lok &= all_ones(__ldcs(sp + i * 32 + lane));
        }
        const bool rok = __all_sync(0xFFFFFFFFu, lok);
        if (lane == l) ok = rok;
    }

    out[row] = ok ? 1.0f : 0.0f;
}

extern "C" void kernel_launch(void* const* d_in, const int* in_sizes, int n_in,
                              void* d_out, int out_size)
{
    const uint4* x = (const uint4*)d_in[0];  // float32 bits reinterpreted
    float* out = (float*)d_out;

    const int rows = out_size;                              // 65536
    const int blocks = (rows + THREADS - 1) / THREADS;      // 128

    vec_and_tree_kernel<<<blocks, THREADS>>>(x, out, rows);
}